// round 9
// baseline (speedup 1.0000x reference)
#include <cuda_runtime.h>
#include <math.h>

#define M_GT 128
#define BLOCK 256

// Per-GT best-anchor key: (iou_bits << 32) | (0xFFFFFFFF - anchor_idx).
// IoU >= 0 so float bit pattern is order-preserving; ~idx makes smaller
// anchor index win ties under max (matches jnp.argmax axis=0 tie-break).
__device__ unsigned long long g_gt_key[M_GT];

__global__ void init_keys_kernel() {
    int t = threadIdx.x;
    if (t < M_GT) g_gt_key[t] = 0ULL;
}

__device__ __forceinline__ unsigned long long pack_key(float iou, int idx) {
    return (((unsigned long long)__float_as_uint(iou)) << 32) |
           (unsigned long long)(0xFFFFFFFFu - (unsigned)idx);
}

__device__ __forceinline__ void encode_write(float* __restrict__ out, int N,
                                             float4 a, float4 g, int i,
                                             bool pos, bool aligned4) {
    const float EPS = 1.1920929e-07f;  // jnp.finfo(float32).eps
    float ax = (a.x + a.z) * 0.5f;
    float ay = (a.y + a.w) * 0.5f;
    float aw = fmaxf(a.z - a.x, EPS);
    float ah = fmaxf(a.w - a.y, EPS);
    float gx = (g.x + g.z) * 0.5f;
    float gy = (g.y + g.w) * 0.5f;
    float gw = g.z - g.x;
    float gh = g.w - g.y;
    float dx = (gx - ax) / aw;
    float dy = (gy - ay) / ah;
    float dw = logf(gw / aw);
    float dh = logf(gh / ah);
    if (!pos) { dx = 0.0f; dy = 0.0f; dw = 0.0f; dh = 0.0f; }
    if (aligned4) {
        ((float4*)(out + N))[i] = make_float4(dx, dy, dw, dh);
    } else {
        float* r = out + N + 4 * i;
        r[0] = dx; r[1] = dy; r[2] = dw; r[3] = dh;
    }
}

__global__ void __launch_bounds__(BLOCK)
match_kernel(const float4* __restrict__ anchors,
             const float4* __restrict__ gts,
             const int* __restrict__ labels,
             float* __restrict__ out,
             int N, int M, int aligned4)
{
    __shared__ float4 sgt[M_GT];
    __shared__ float  sarea[M_GT];
    __shared__ int    slab[M_GT];
    __shared__ unsigned long long skey[M_GT];

    int tid = threadIdx.x;
    for (int j = tid; j < M_GT; j += BLOCK) {
        if (j < M) {
            float4 g = gts[j];
            sgt[j]   = g;
            sarea[j] = (g.z - g.x) * (g.w - g.y);
            slab[j]  = labels[j];
        }
        skey[j] = 0ULL;
    }
    __syncthreads();

    int  i      = blockIdx.x * BLOCK + tid;
    bool active = (i < N);
    float4 a    = anchors[active ? i : 0];
    float area_a = (a.z - a.x) * (a.w - a.y);

    int lane  = tid & 31;
    float best = -1.0f;
    int   bestj = 0;

    for (int j = 0; j < M; ++j) {
        float4 g = sgt[j];
        float lx = fmaxf(a.x, g.x);
        float ly = fmaxf(a.y, g.y);
        float rx = fminf(a.z, g.z);
        float ry = fminf(a.w, g.w);
        float w  = fmaxf(rx - lx, 0.0f);
        float h  = fmaxf(ry - ly, 0.0f);
        float inter = w * h;
        float iou   = inter / (area_a + sarea[j] - inter);
        float iou_r = active ? iou : -1.0f;       // inactive lanes never win

        // per-anchor argmax over GTs: strict '>' keeps first j (jnp tie-break)
        if (iou_r > best) { best = iou_r; bestj = j; }

        // per-GT warp argmax: warp max value, lowest matching lane writes.
        // Consecutive lanes = consecutive anchor indices, so lowest lane is
        // the correct (smallest-index) tie-break within the warp.
        float m = iou_r;
        #pragma unroll
        for (int off = 16; off; off >>= 1)
            m = fmaxf(m, __shfl_xor_sync(0xFFFFFFFFu, m, off));
        unsigned bal = __ballot_sync(0xFFFFFFFFu, (iou_r == m) && active);
        if (bal) {
            int src = __ffs(bal) - 1;
            if (lane == src)
                atomicMax(&skey[j], pack_key(iou, i));
        }
    }
    __syncthreads();
    if (tid < M)
        atomicMax(&g_gt_key[tid], skey[tid]);   // one L2 atomic per (block,GT)

    if (!active) return;

    bool pos = (best >= 0.5f);
    bool neg = (best < 0.4f) && !pos;
    int  cls = pos ? slab[bestj] : (neg ? 0 : -1);

    out[i] = (float)cls;
    encode_write(out, N, a, sgt[bestj], i, pos, aligned4 != 0);
    out[5 * N + i] = pos ? 1.0f : 0.0f;
}

// Force best-anchor-per-GT positive. Recomputes that anchor's own matched
// GT (per-anchor argmax) — identical values from any thread sharing the
// same anchor, so concurrent duplicate writes are deterministic.
__global__ void fix_kernel(const float4* __restrict__ anchors,
                           const float4* __restrict__ gts,
                           const int* __restrict__ labels,
                           float* __restrict__ out,
                           int N, int M, int aligned4)
{
    __shared__ float4 sgt[M_GT];
    __shared__ float  sarea[M_GT];
    int t = threadIdx.x;
    if (t < M) {
        float4 g = gts[t];
        sgt[t]   = g;
        sarea[t] = (g.z - g.x) * (g.w - g.y);
    }
    __syncthreads();
    if (t >= M) return;

    unsigned long long key = g_gt_key[t];
    int idx = (int)(0xFFFFFFFFu - (unsigned)(key & 0xFFFFFFFFULL));
    if (idx < 0 || idx >= N) return;   // safety (cannot happen in practice)

    float4 a = anchors[idx];
    float area_a = (a.z - a.x) * (a.w - a.y);
    float best = -1.0f;
    int   bestj = 0;
    for (int j = 0; j < M; ++j) {
        float4 g = sgt[j];
        float lx = fmaxf(a.x, g.x);
        float ly = fmaxf(a.y, g.y);
        float rx = fminf(a.z, g.z);
        float ry = fminf(a.w, g.w);
        float w  = fmaxf(rx - lx, 0.0f);
        float h  = fmaxf(ry - ly, 0.0f);
        float inter = w * h;
        float iou   = inter / (area_a + sarea[j] - inter);
        if (iou > best) { best = iou; bestj = j; }
    }

    out[idx] = (float)labels[bestj];
    encode_write(out, N, a, sgt[bestj], idx, true, aligned4 != 0);
    out[5 * N + idx] = 1.0f;
}

extern "C" void kernel_launch(void* const* d_in, const int* in_sizes, int n_in,
                              void* d_out, int out_size)
{
    const float4* anchors = (const float4*)d_in[0];
    const float4* gts     = (const float4*)d_in[1];
    const int*    labels  = (const int*)d_in[2];
    float*        out     = (float*)d_out;

    int N = in_sizes[0] / 4;
    int M = in_sizes[2];
    if (M > M_GT) M = M_GT;
    int aligned4 = ((N & 3) == 0) ? 1 : 0;

    init_keys_kernel<<<1, 128>>>();
    int blocks = (N + BLOCK - 1) / BLOCK;
    match_kernel<<<blocks, BLOCK>>>(anchors, gts, labels, out, N, M, aligned4);
    fix_kernel<<<1, 128>>>(anchors, gts, labels, out, N, M, aligned4);
}